// round 3
// baseline (speedup 1.0000x reference)
#include <cuda_runtime.h>

#define HID 128
#define H   8
#define HD  16
#define NMAX 50000
#define EMAX 800000

// ---------------- scratch (no allocations allowed) ----------------
__device__ float g_weff_src[HID * H];
__device__ float g_weff_dst[HID * H];
__device__ float g_beff[2 * H];
__device__ float g_alpha_src[NMAX * H];
__device__ float g_alpha_dst[NMAX * H];
__device__ int   g_count[NMAX];
__device__ int   g_offsets[NMAX + 1];
__device__ int   g_cursor[NMAX];
__device__ int   g_src_sorted[EMAX];
__device__ float g_scores[EMAX * H];     // sorted by dst node
__device__ float g_agg[NMAX * HID];

// ---------------- fold att_w into node_w ----------------
__global__ void k_prep(const float* __restrict__ node_w,
                       const float* __restrict__ node_b,
                       const float* __restrict__ att_w) {
    int t = threadIdx.x;
    for (int p = t; p < HID * H; p += blockDim.x) {
        int k = p / H, h = p % H;
        float ss = 0.f, sd = 0.f;
        #pragma unroll
        for (int d = 0; d < HD; d++) {
            ss += node_w[k * (2 * HID) + h * (2 * HD) + d]       * att_w[h * (2 * HD) + d];
            sd += node_w[k * (2 * HID) + h * (2 * HD) + HD + d]  * att_w[h * (2 * HD) + HD + d];
        }
        g_weff_src[k * H + h] = ss;
        g_weff_dst[k * H + h] = sd;
    }
    if (t < H) {
        float bs = 0.f, bd = 0.f;
        #pragma unroll
        for (int d = 0; d < HD; d++) {
            bs += node_b[t * (2 * HD) + d]      * att_w[t * (2 * HD) + d];
            bd += node_b[t * (2 * HD) + HD + d] * att_w[t * (2 * HD) + HD + d];
        }
        g_beff[t]     = bs;
        g_beff[H + t] = bd;
    }
}

__global__ void k_zero(int n) {
    int i = blockIdx.x * blockDim.x + threadIdx.x;
    if (i < n) g_count[i] = 0;
}

// ---------------- per-node alpha (X @ w_eff) ----------------
__global__ void k_alpha(const float* __restrict__ X, int n) {
    __shared__ float ws[HID * H];
    __shared__ float wd[HID * H];
    for (int i = threadIdx.x; i < HID * H; i += blockDim.x) {
        ws[i] = g_weff_src[i];
        wd[i] = g_weff_dst[i];
    }
    __syncthreads();
    int idx = blockIdx.x * blockDim.x + threadIdx.x;
    if (idx >= n * H) return;
    int node = idx / H, h = idx % H;
    const float4* x4 = (const float4*)(X + (size_t)node * HID);
    float as = g_beff[h], ad = g_beff[H + h];
    #pragma unroll
    for (int k4 = 0; k4 < HID / 4; k4++) {
        float4 xv = x4[k4];
        int k = k4 * 4;
        as += xv.x * ws[(k + 0) * H + h] + xv.y * ws[(k + 1) * H + h]
            + xv.z * ws[(k + 2) * H + h] + xv.w * ws[(k + 3) * H + h];
        ad += xv.x * wd[(k + 0) * H + h] + xv.y * wd[(k + 1) * H + h]
            + xv.z * wd[(k + 2) * H + h] + xv.w * wd[(k + 3) * H + h];
    }
    g_alpha_src[idx] = as;
    g_alpha_dst[idx] = ad;
}

// ---------------- degree histogram (edge_index is int32) ----------------
__global__ void k_count(const int* __restrict__ ei, int e, int n) {
    int i = blockIdx.x * blockDim.x + threadIdx.x;
    if (i < e) {
        int c = ei[e + i];
        c = min(max(c, 0), n - 1);
        atomicAdd(&g_count[c], 1);
    }
}

// ---------------- single-block exclusive scan over N counts ----------------
__global__ void k_scan(int n) {
    __shared__ int warp_sums[32];
    __shared__ int s_carry;
    int tid = threadIdx.x, lane = tid & 31, wid = tid >> 5;
    if (tid == 0) s_carry = 0;
    __syncthreads();
    for (int base = 0; base < n; base += 1024) {
        int i = base + tid;
        int v = (i < n) ? g_count[i] : 0;
        int x = v;
        #pragma unroll
        for (int o = 1; o < 32; o <<= 1) {
            int y = __shfl_up_sync(0xffffffffu, x, o);
            if (lane >= o) x += y;
        }
        if (lane == 31) warp_sums[wid] = x;
        __syncthreads();
        if (wid == 0) {
            int s = warp_sums[lane];
            #pragma unroll
            for (int o = 1; o < 32; o <<= 1) {
                int y = __shfl_up_sync(0xffffffffu, s, o);
                if (lane >= o) s += y;
            }
            warp_sums[lane] = s;
        }
        __syncthreads();
        int warp_off = (wid > 0) ? warp_sums[wid - 1] : 0;
        int incl = x + warp_off + s_carry;
        int excl = incl - v;
        if (i < n) {
            g_offsets[i] = excl;
            g_cursor[i]  = excl;
        }
        __syncthreads();
        if (tid == blockDim.x - 1) s_carry = incl;
        __syncthreads();
    }
    if (tid == 0) g_offsets[n] = s_carry;
}

// ---------------- scores + scatter into CSR slots ----------------
__global__ void k_score(const int* __restrict__ ei, int e, int n) {
    int i = blockIdx.x * blockDim.x + threadIdx.x;
    if (i >= e) return;
    int row = ei[i];
    int col = ei[e + i];
    row = min(max(row, 0), n - 1);
    col = min(max(col, 0), n - 1);
    const float4* as4 = (const float4*)(g_alpha_src + (size_t)row * H);
    const float4* ad4 = (const float4*)(g_alpha_dst + (size_t)col * H);
    float4 a0 = as4[0], a1 = as4[1];
    float4 b0 = ad4[0], b1 = ad4[1];
    float s[8];
    s[0] = a0.x + b0.x; s[1] = a0.y + b0.y; s[2] = a0.z + b0.z; s[3] = a0.w + b0.w;
    s[4] = a1.x + b1.x; s[5] = a1.y + b1.y; s[6] = a1.z + b1.z; s[7] = a1.w + b1.w;
    #pragma unroll
    for (int h = 0; h < 8; h++) s[h] = (s[h] >= 0.f) ? s[h] : 0.2f * s[h];
    int pos = atomicAdd(&g_cursor[col], 1);
    g_src_sorted[pos] = row;
    float4* out = (float4*)(g_scores + (size_t)pos * 8);
    out[0] = make_float4(s[0], s[1], s[2], s[3]);
    out[1] = make_float4(s[4], s[5], s[6], s[7]);
}

// ---------------- warp-per-dst-node softmax + gather-aggregate ----------------
__global__ void k_agg(const float* __restrict__ X, int n) {
    __shared__ float sp[8][32][9];   // +1 pad: conflict-free stores
    __shared__ int   ssrc[8][32];
    int w = threadIdx.x >> 5, lane = threadIdx.x & 31;
    int node = blockIdx.x * 8 + w;
    if (node >= n) return;
    int start = g_offsets[node];
    int end   = g_offsets[node + 1];

    // pass 1: per-head max (clamped at 0, matching max(seg_max, 0))
    float m[8];
    #pragma unroll
    for (int h = 0; h < 8; h++) m[h] = 0.f;
    for (int j = start + lane; j < end; j += 32) {
        const float4* s4 = (const float4*)(g_scores + (size_t)j * 8);
        float4 a = s4[0], b = s4[1];
        m[0] = fmaxf(m[0], a.x); m[1] = fmaxf(m[1], a.y);
        m[2] = fmaxf(m[2], a.z); m[3] = fmaxf(m[3], a.w);
        m[4] = fmaxf(m[4], b.x); m[5] = fmaxf(m[5], b.y);
        m[6] = fmaxf(m[6], b.z); m[7] = fmaxf(m[7], b.w);
    }
    #pragma unroll
    for (int o = 16; o > 0; o >>= 1)
        #pragma unroll
        for (int h = 0; h < 8; h++)
            m[h] = fmaxf(m[h], __shfl_xor_sync(0xffffffffu, m[h], o));

    // pass 2: exp + denom + weighted gather
    float acc0 = 0.f, acc1 = 0.f, acc2 = 0.f, acc3 = 0.f;
    float den[8];
    #pragma unroll
    for (int h = 0; h < 8; h++) den[h] = 0.f;

    const int h0 = (lane)      >> 4;
    const int h1 = (lane + 32) >> 4;
    const int h2 = (lane + 64) >> 4;
    const int h3 = (lane + 96) >> 4;

    for (int j0 = start; j0 < end; j0 += 32) {
        int j = j0 + lane;
        float p[8];
        int src = 0;
        if (j < end) {
            const float4* s4 = (const float4*)(g_scores + (size_t)j * 8);
            float4 a = s4[0], b = s4[1];
            p[0] = __expf(a.x - m[0]); p[1] = __expf(a.y - m[1]);
            p[2] = __expf(a.z - m[2]); p[3] = __expf(a.w - m[3]);
            p[4] = __expf(b.x - m[4]); p[5] = __expf(b.y - m[5]);
            p[6] = __expf(b.z - m[6]); p[7] = __expf(b.w - m[7]);
            #pragma unroll
            for (int h = 0; h < 8; h++) den[h] += p[h];
            src = g_src_sorted[j];
        } else {
            #pragma unroll
            for (int h = 0; h < 8; h++) p[h] = 0.f;
        }
        #pragma unroll
        for (int h = 0; h < 8; h++) sp[w][lane][h] = p[h];
        ssrc[w][lane] = src;
        __syncwarp();
        int cnt = min(32, end - j0);
        for (int t = 0; t < cnt; t++) {
            const float* xr = X + (size_t)ssrc[w][t] * HID;
            acc0 += sp[w][t][h0] * xr[lane];
            acc1 += sp[w][t][h1] * xr[lane + 32];
            acc2 += sp[w][t][h2] * xr[lane + 64];
            acc3 += sp[w][t][h3] * xr[lane + 96];
        }
        __syncwarp();
    }
    #pragma unroll
    for (int o = 16; o > 0; o >>= 1)
        #pragma unroll
        for (int h = 0; h < 8; h++)
            den[h] += __shfl_xor_sync(0xffffffffu, den[h], o);

    float* outp = g_agg + (size_t)node * HID;
    outp[lane]      = acc0 / (den[h0] + 1e-10f);
    outp[lane + 32] = acc1 / (den[h1] + 1e-10f);
    outp[lane + 64] = acc2 / (den[h2] + 1e-10f);
    outp[lane + 96] = acc3 / (den[h3] + 1e-10f);
}

// ---------------- out = agg @ out_w + out_b  (64x64 tiles, 4x4 micro) ----------------
__global__ void k_gemm(const float* __restrict__ W,
                       const float* __restrict__ bias,
                       float* __restrict__ out, int n) {
    __shared__ float As[16][68];   // [k][m], padded
    __shared__ float Bs[16][68];   // [k][c], padded
    int tx = threadIdx.x & 15;     // col group
    int ty = threadIdx.x >> 4;     // row group
    int m0 = blockIdx.x * 64;
    int c0 = blockIdx.y * 64;
    float acc[4][4];
    #pragma unroll
    for (int i = 0; i < 4; i++)
        #pragma unroll
        for (int j = 0; j < 4; j++) acc[i][j] = 0.f;

    for (int kt = 0; kt < HID; kt += 16) {
        {
            int t = threadIdx.x;
            int mm = t >> 2, q = t & 3;
            int row = m0 + mm;
            float4 v = make_float4(0.f, 0.f, 0.f, 0.f);
            if (row < n)
                v = *(const float4*)(g_agg + (size_t)row * HID + kt + q * 4);
            As[q * 4 + 0][mm] = v.x;
            As[q * 4 + 1][mm] = v.y;
            As[q * 4 + 2][mm] = v.z;
            As[q * 4 + 3][mm] = v.w;
        }
        {
            int t = threadIdx.x;
            int kk = t >> 4, cq = t & 15;
            float4 v = *(const float4*)(W + (size_t)(kt + kk) * HID + c0 + cq * 4);
            *(float4*)&Bs[kk][cq * 4] = v;
        }
        __syncthreads();
        #pragma unroll
        for (int k = 0; k < 16; k++) {
            float4 a = *(const float4*)&As[k][ty * 4];
            float4 b = *(const float4*)&Bs[k][tx * 4];
            acc[0][0] += a.x * b.x; acc[0][1] += a.x * b.y; acc[0][2] += a.x * b.z; acc[0][3] += a.x * b.w;
            acc[1][0] += a.y * b.x; acc[1][1] += a.y * b.y; acc[1][2] += a.y * b.z; acc[1][3] += a.y * b.w;
            acc[2][0] += a.z * b.x; acc[2][1] += a.z * b.y; acc[2][2] += a.z * b.z; acc[2][3] += a.z * b.w;
            acc[3][0] += a.w * b.x; acc[3][1] += a.w * b.y; acc[3][2] += a.w * b.z; acc[3][3] += a.w * b.w;
        }
        __syncthreads();
    }
    #pragma unroll
    for (int i = 0; i < 4; i++) {
        int row = m0 + ty * 4 + i;
        if (row >= n) continue;
        #pragma unroll
        for (int j = 0; j < 4; j++) {
            int c = c0 + tx * 4 + j;
            out[(size_t)row * HID + c] = acc[i][j] + bias[c];
        }
    }
}

extern "C" void kernel_launch(void* const* d_in, const int* in_sizes, int n_in,
                              void* d_out, int out_size) {
    const float* X      = (const float*)d_in[0];
    const int*   ei     = (const int*)d_in[1];
    const float* node_w = (const float*)d_in[2];
    const float* node_b = (const float*)d_in[3];
    const float* att_w  = (const float*)d_in[4];
    const float* out_w  = (const float*)d_in[5];
    const float* out_b  = (const float*)d_in[6];
    float*       out    = (float*)d_out;

    int n = in_sizes[0] / HID;
    int e = in_sizes[1] / 2;

    k_prep <<<1, 256>>>(node_w, node_b, att_w);
    k_zero <<<(n + 255) / 256, 256>>>(n);
    k_alpha<<<(n * H + 255) / 256, 256>>>(X, n);
    k_count<<<(e + 255) / 256, 256>>>(ei, e, n);
    k_scan <<<1, 1024>>>(n);
    k_score<<<(e + 255) / 256, 256>>>(ei, e, n);
    k_agg  <<<(n + 7) / 8, 256>>>(X, n);
    dim3 gg((n + 63) / 64, HID / 64);
    k_gemm <<<gg, 256>>>(out_w, out_b, out, n);
}

// round 4
// speedup vs baseline: 1.2018x; 1.2018x over previous
#include <cuda_runtime.h>

#define HID 128
#define H   8
#define HD  16
#define NMAX 50000
#define EMAX 800000

// ---------------- scratch (no allocations allowed) ----------------
__device__ float g_weff_src[HID * H];
__device__ float g_weff_dst[HID * H];
__device__ float g_beff[2 * H];
__device__ float g_alpha_src[NMAX * H];
__device__ float g_alpha_dst[NMAX * H];
__device__ int   g_count[NMAX];
__device__ int   g_offsets[NMAX + 1];
__device__ int   g_cursor[NMAX];
__device__ int   g_src_sorted[EMAX];
__device__ float g_agg[NMAX * HID];

// ---------------- fold att_w into node_w ----------------
__global__ void k_prep(const float* __restrict__ node_w,
                       const float* __restrict__ node_b,
                       const float* __restrict__ att_w) {
    int t = threadIdx.x;
    for (int p = t; p < HID * H; p += blockDim.x) {
        int k = p / H, h = p % H;
        float ss = 0.f, sd = 0.f;
        #pragma unroll
        for (int d = 0; d < HD; d++) {
            ss += node_w[k * (2 * HID) + h * (2 * HD) + d]       * att_w[h * (2 * HD) + d];
            sd += node_w[k * (2 * HID) + h * (2 * HD) + HD + d]  * att_w[h * (2 * HD) + HD + d];
        }
        g_weff_src[k * H + h] = ss;
        g_weff_dst[k * H + h] = sd;
    }
    if (t < H) {
        float bs = 0.f, bd = 0.f;
        #pragma unroll
        for (int d = 0; d < HD; d++) {
            bs += node_b[t * (2 * HD) + d]      * att_w[t * (2 * HD) + d];
            bd += node_b[t * (2 * HD) + HD + d] * att_w[t * (2 * HD) + HD + d];
        }
        g_beff[t]     = bs;
        g_beff[H + t] = bd;
    }
}

__global__ void k_zero(int n) {
    int i = blockIdx.x * blockDim.x + threadIdx.x;
    if (i < n) g_count[i] = 0;
}

// ---------------- per-node alpha (X @ w_eff) ----------------
__global__ void k_alpha(const float* __restrict__ X, int n) {
    __shared__ float ws[HID * H];
    __shared__ float wd[HID * H];
    for (int i = threadIdx.x; i < HID * H; i += blockDim.x) {
        ws[i] = g_weff_src[i];
        wd[i] = g_weff_dst[i];
    }
    __syncthreads();
    int idx = blockIdx.x * blockDim.x + threadIdx.x;
    if (idx >= n * H) return;
    int node = idx / H, h = idx % H;
    const float4* x4 = (const float4*)(X + (size_t)node * HID);
    float as = g_beff[h], ad = g_beff[H + h];
    #pragma unroll
    for (int k4 = 0; k4 < HID / 4; k4++) {
        float4 xv = x4[k4];
        int k = k4 * 4;
        as += xv.x * ws[(k + 0) * H + h] + xv.y * ws[(k + 1) * H + h]
            + xv.z * ws[(k + 2) * H + h] + xv.w * ws[(k + 3) * H + h];
        ad += xv.x * wd[(k + 0) * H + h] + xv.y * wd[(k + 1) * H + h]
            + xv.z * wd[(k + 2) * H + h] + xv.w * wd[(k + 3) * H + h];
    }
    g_alpha_src[idx] = as;
    g_alpha_dst[idx] = ad;
}

// ---------------- degree histogram (edge_index is int32) ----------------
__global__ void k_count(const int* __restrict__ ei, int e, int n) {
    int i = blockIdx.x * blockDim.x + threadIdx.x;
    if (i < e) {
        int c = ei[e + i];
        c = min(max(c, 0), n - 1);
        atomicAdd(&g_count[c], 1);
    }
}

// ---------------- single-block exclusive scan over N counts ----------------
__global__ void k_scan(int n) {
    __shared__ int warp_sums[32];
    __shared__ int s_carry;
    int tid = threadIdx.x, lane = tid & 31, wid = tid >> 5;
    if (tid == 0) s_carry = 0;
    __syncthreads();
    for (int base = 0; base < n; base += 1024) {
        int i = base + tid;
        int v = (i < n) ? g_count[i] : 0;
        int x = v;
        #pragma unroll
        for (int o = 1; o < 32; o <<= 1) {
            int y = __shfl_up_sync(0xffffffffu, x, o);
            if (lane >= o) x += y;
        }
        if (lane == 31) warp_sums[wid] = x;
        __syncthreads();
        if (wid == 0) {
            int s = warp_sums[lane];
            #pragma unroll
            for (int o = 1; o < 32; o <<= 1) {
                int y = __shfl_up_sync(0xffffffffu, s, o);
                if (lane >= o) s += y;
            }
            warp_sums[lane] = s;
        }
        __syncthreads();
        int warp_off = (wid > 0) ? warp_sums[wid - 1] : 0;
        int incl = x + warp_off + s_carry;
        int excl = incl - v;
        if (i < n) {
            g_offsets[i] = excl;
            g_cursor[i]  = excl;
        }
        __syncthreads();
        if (tid == blockDim.x - 1) s_carry = incl;
        __syncthreads();
    }
    if (tid == 0) g_offsets[n] = s_carry;
}

// ---------------- permutation scatter into CSR slots (src only) ----------------
__global__ void k_scatter(const int* __restrict__ ei, int e, int n) {
    int i = blockIdx.x * blockDim.x + threadIdx.x;
    if (i >= e) return;
    int row = ei[i];
    int col = ei[e + i];
    row = min(max(row, 0), n - 1);
    col = min(max(col, 0), n - 1);
    int pos = atomicAdd(&g_cursor[col], 1);
    g_src_sorted[pos] = row;
}

// ---- fused: scores + softmax (shift-free) + weighted gather, warp/node ----
__global__ void k_agg(const float* __restrict__ X, int n) {
    __shared__ float sp[8][32][9];   // [warp][edge-in-group][head], pad 9
    __shared__ int   ssrc[8][32];
    int w = threadIdx.x >> 5, lane = threadIdx.x & 31;
    int node = blockIdx.x * 8 + w;
    if (node >= n) return;
    int start = g_offsets[node];
    int end   = g_offsets[node + 1];

    // per-node alpha_dst (broadcast load, 32B)
    const float4* bd4 = (const float4*)(g_alpha_dst + (size_t)node * H);
    float4 bd0 = bd4[0], bd1 = bd4[1];

    float den[8];
    #pragma unroll
    for (int h = 0; h < 8; h++) den[h] = 0.f;
    float4 acc = make_float4(0.f, 0.f, 0.f, 0.f);
    const int hsel = lane >> 2;                 // head for my 4 channels

    for (int j0 = start; j0 < end; j0 += 32) {
        int j = j0 + lane;
        float p[8];
        int src = 0;
        if (j < end) {
            src = g_src_sorted[j];
            const float4* as4 = (const float4*)(g_alpha_src + (size_t)src * H);
            float4 a0 = as4[0], a1 = as4[1];
            float s[8];
            s[0] = a0.x + bd0.x; s[1] = a0.y + bd0.y;
            s[2] = a0.z + bd0.z; s[3] = a0.w + bd0.w;
            s[4] = a1.x + bd1.x; s[5] = a1.y + bd1.y;
            s[6] = a1.z + bd1.z; s[7] = a1.w + bd1.w;
            #pragma unroll
            for (int h = 0; h < 8; h++) {
                float v = (s[h] >= 0.f) ? s[h] : 0.2f * s[h];
                p[h] = __expf(v);
                den[h] += p[h];
            }
        } else {
            #pragma unroll
            for (int h = 0; h < 8; h++) p[h] = 0.f;
        }
        #pragma unroll
        for (int h = 0; h < 8; h++) sp[w][lane][h] = p[h];
        ssrc[w][lane] = src;
        __syncwarp();
        int cnt = min(32, end - j0);
        #pragma unroll 4
        for (int t = 0; t < cnt; t++) {
            const float4* xr = (const float4*)(X + (size_t)ssrc[w][t] * HID);
            float pw = sp[w][t][hsel];
            float4 xv = xr[lane];
            acc.x += pw * xv.x;
            acc.y += pw * xv.y;
            acc.z += pw * xv.z;
            acc.w += pw * xv.w;
        }
        __syncwarp();
    }
    #pragma unroll
    for (int o = 16; o > 0; o >>= 1)
        #pragma unroll
        for (int h = 0; h < 8; h++)
            den[h] += __shfl_xor_sync(0xffffffffu, den[h], o);

    float inv = 1.f / (den[hsel] + 1e-10f);
    float4 outv = make_float4(acc.x * inv, acc.y * inv, acc.z * inv, acc.w * inv);
    ((float4*)(g_agg + (size_t)node * HID))[lane] = outv;
}

// ---------------- out = agg @ out_w + out_b  (64x64 tiles, 4x4 micro) ----------------
__global__ void k_gemm(const float* __restrict__ W,
                       const float* __restrict__ bias,
                       float* __restrict__ out, int n) {
    __shared__ float As[16][68];   // [k][m], padded
    __shared__ float Bs[16][68];   // [k][c], padded
    int tx = threadIdx.x & 15;     // col group
    int ty = threadIdx.x >> 4;     // row group
    int m0 = blockIdx.x * 64;
    int c0 = blockIdx.y * 64;
    float acc[4][4];
    #pragma unroll
    for (int i = 0; i < 4; i++)
        #pragma unroll
        for (int j = 0; j < 4; j++) acc[i][j] = 0.f;

    for (int kt = 0; kt < HID; kt += 16) {
        {
            int t = threadIdx.x;
            int mm = t >> 2, q = t & 3;
            int row = m0 + mm;
            float4 v = make_float4(0.f, 0.f, 0.f, 0.f);
            if (row < n)
                v = *(const float4*)(g_agg + (size_t)row * HID + kt + q * 4);
            As[q * 4 + 0][mm] = v.x;
            As[q * 4 + 1][mm] = v.y;
            As[q * 4 + 2][mm] = v.z;
            As[q * 4 + 3][mm] = v.w;
        }
        {
            int t = threadIdx.x;
            int kk = t >> 4, cq = t & 15;
            float4 v = *(const float4*)(W + (size_t)(kt + kk) * HID + c0 + cq * 4);
            *(float4*)&Bs[kk][cq * 4] = v;
        }
        __syncthreads();
        #pragma unroll
        for (int k = 0; k < 16; k++) {
            float4 a = *(const float4*)&As[k][ty * 4];
            float4 b = *(const float4*)&Bs[k][tx * 4];
            acc[0][0] += a.x * b.x; acc[0][1] += a.x * b.y; acc[0][2] += a.x * b.z; acc[0][3] += a.x * b.w;
            acc[1][0] += a.y * b.x; acc[1][1] += a.y * b.y; acc[1][2] += a.y * b.z; acc[1][3] += a.y * b.w;
            acc[2][0] += a.z * b.x; acc[2][1] += a.z * b.y; acc[2][2] += a.z * b.z; acc[2][3] += a.z * b.w;
            acc[3][0] += a.w * b.x; acc[3][1] += a.w * b.y; acc[3][2] += a.w * b.z; acc[3][3] += a.w * b.w;
        }
        __syncthreads();
    }
    #pragma unroll
    for (int i = 0; i < 4; i++) {
        int row = m0 + ty * 4 + i;
        if (row >= n) continue;
        #pragma unroll
        for (int j = 0; j < 4; j++) {
            int c = c0 + tx * 4 + j;
            out[(size_t)row * HID + c] = acc[i][j] + bias[c];
        }
    }
}

extern "C" void kernel_launch(void* const* d_in, const int* in_sizes, int n_in,
                              void* d_out, int out_size) {
    const float* X      = (const float*)d_in[0];
    const int*   ei     = (const int*)d_in[1];
    const float* node_w = (const float*)d_in[2];
    const float* node_b = (const float*)d_in[3];
    const float* att_w  = (const float*)d_in[4];
    const float* out_w  = (const float*)d_in[5];
    const float* out_b  = (const float*)d_in[6];
    float*       out    = (float*)d_out;

    int n = in_sizes[0] / HID;
    int e = in_sizes[1] / 2;

    k_prep   <<<1, 256>>>(node_w, node_b, att_w);
    k_zero   <<<(n + 255) / 256, 256>>>(n);
    k_alpha  <<<(n * H + 255) / 256, 256>>>(X, n);
    k_count  <<<(e + 255) / 256, 256>>>(ei, e, n);
    k_scan   <<<1, 1024>>>(n);
    k_scatter<<<(e + 255) / 256, 256>>>(ei, e, n);
    k_agg    <<<(n + 7) / 8, 256>>>(X, n);
    dim3 gg((n + 63) / 64, HID / 64);
    k_gemm   <<<gg, 256>>>(out_w, out_b, out, n);
}

// round 5
// speedup vs baseline: 1.2609x; 1.0492x over previous
#include <cuda_runtime.h>

#define HID 128
#define H   8
#define HD  16
#define NMAX 50000
#define EMAX 800000
#define SCAN_B 256

// ---------------- scratch (no allocations allowed) ----------------
__device__ float g_weff_src[HID * H];
__device__ float g_weff_dst[HID * H];
__device__ float g_beff[2 * H];
__device__ float g_alpha_src[NMAX * H];
__device__ float g_alpha_dst[NMAX * H];
__device__ int   g_count[NMAX];
__device__ int   g_offsets[NMAX + 1];
__device__ int   g_cursor[NMAX];
__device__ int   g_src_sorted[EMAX];
__device__ int   g_bsum[512];
__device__ float g_agg[NMAX * HID];

// ---------------- zero counts + fold att_w into node_w (block 0) ----------------
__global__ void k_init(const float* __restrict__ node_w,
                       const float* __restrict__ node_b,
                       const float* __restrict__ att_w, int n) {
    int i = blockIdx.x * blockDim.x + threadIdx.x;
    if (i < n) g_count[i] = 0;
    if (blockIdx.x == 0) {
        int t = threadIdx.x;
        for (int p = t; p < HID * H; p += blockDim.x) {
            int k = p / H, h = p % H;
            float ss = 0.f, sd = 0.f;
            #pragma unroll
            for (int d = 0; d < HD; d++) {
                ss += node_w[k * (2 * HID) + h * (2 * HD) + d]      * att_w[h * (2 * HD) + d];
                sd += node_w[k * (2 * HID) + h * (2 * HD) + HD + d] * att_w[h * (2 * HD) + HD + d];
            }
            g_weff_src[k * H + h] = ss;
            g_weff_dst[k * H + h] = sd;
        }
        if (t < H) {
            float bs = 0.f, bd = 0.f;
            #pragma unroll
            for (int d = 0; d < HD; d++) {
                bs += node_b[t * (2 * HD) + d]      * att_w[t * (2 * HD) + d];
                bd += node_b[t * (2 * HD) + HD + d] * att_w[t * (2 * HD) + HD + d];
            }
            g_beff[t]     = bs;
            g_beff[H + t] = bd;
        }
    }
}

// ---------------- warp-per-node alpha (row read ONCE, coalesced) ----------------
__global__ void k_alpha(const float* __restrict__ X, int n) {
    __shared__ float sw[16][HID];   // [src0..7,dst0..7][k]
    int tid = threadIdx.x;
    for (int idx = tid; idx < 16 * HID; idx += blockDim.x) {
        int hh = idx >> 7, k = idx & 127;
        sw[hh][k] = (hh < 8) ? g_weff_src[k * H + hh] : g_weff_dst[k * H + (hh - 8)];
    }
    __syncthreads();
    int w = tid >> 5, lane = tid & 31;
    int node = blockIdx.x * 8 + w;
    if (node >= n) return;
    float4 xv = ((const float4*)(X + (size_t)node * HID))[lane];
    float r[16];
    #pragma unroll
    for (int hh = 0; hh < 16; hh++) {
        float4 wv = *(const float4*)&sw[hh][lane * 4];
        r[hh] = xv.x * wv.x + xv.y * wv.y + xv.z * wv.z + xv.w * wv.w;
    }
    #pragma unroll
    for (int o = 16; o > 0; o >>= 1)
        #pragma unroll
        for (int hh = 0; hh < 16; hh++)
            r[hh] += __shfl_xor_sync(0xffffffffu, r[hh], o);
    if (lane == 0) {
        float4* ps = (float4*)(g_alpha_src + (size_t)node * H);
        ps[0] = make_float4(r[0] + g_beff[0], r[1] + g_beff[1], r[2] + g_beff[2], r[3] + g_beff[3]);
        ps[1] = make_float4(r[4] + g_beff[4], r[5] + g_beff[5], r[6] + g_beff[6], r[7] + g_beff[7]);
        float4* pd = (float4*)(g_alpha_dst + (size_t)node * H);
        pd[0] = make_float4(r[8]  + g_beff[8],  r[9]  + g_beff[9],  r[10] + g_beff[10], r[11] + g_beff[11]);
        pd[1] = make_float4(r[12] + g_beff[12], r[13] + g_beff[13], r[14] + g_beff[14], r[15] + g_beff[15]);
    }
}

// ---------------- degree histogram (edge_index is int32) ----------------
__global__ void k_count(const int* __restrict__ ei, int e, int n) {
    int i = blockIdx.x * blockDim.x + threadIdx.x;
    if (i < e) {
        int c = ei[e + i];
        c = min(max(c, 0), n - 1);
        atomicAdd(&g_count[c], 1);
    }
}

// ---------------- 3-phase parallel scan ----------------
__global__ void k_scan1(int n) {           // per-block sums
    __shared__ int wsum[8];
    int tid = threadIdx.x, lane = tid & 31, wid = tid >> 5;
    int i = blockIdx.x * SCAN_B + tid;
    int v = (i < n) ? g_count[i] : 0;
    #pragma unroll
    for (int o = 16; o > 0; o >>= 1) v += __shfl_xor_sync(0xffffffffu, v, o);
    if (lane == 0) wsum[wid] = v;
    __syncthreads();
    if (tid == 0) {
        int s = 0;
        #pragma unroll
        for (int k = 0; k < 8; k++) s += wsum[k];
        g_bsum[blockIdx.x] = s;
    }
}

__global__ void k_scan2(int nb, int n) {   // exclusive scan of <=512 block sums (1 block, 512 thr)
    __shared__ int wsum[16];
    int tid = threadIdx.x, lane = tid & 31, wid = tid >> 5;
    int v = (tid < nb) ? g_bsum[tid] : 0;
    int x = v;
    #pragma unroll
    for (int o = 1; o < 32; o <<= 1) {
        int y = __shfl_up_sync(0xffffffffu, x, o);
        if (lane >= o) x += y;
    }
    if (lane == 31) wsum[wid] = x;
    __syncthreads();
    if (wid == 0 && lane < 16) {
        int s = wsum[lane];
        #pragma unroll
        for (int o = 1; o < 16; o <<= 1) {
            int y = __shfl_up_sync(0xffffu, s, o);
            if (lane >= o) s += y;
        }
        wsum[lane] = s;
    }
    __syncthreads();
    int off = (wid > 0) ? wsum[wid - 1] : 0;
    int excl = x - v + off;
    if (tid < nb) g_bsum[tid] = excl;
    if (tid == nb - 1) g_offsets[n] = excl + v;   // total = E
}

__global__ void k_scan3(int n) {           // local scan + base
    __shared__ int wsum[8];
    int tid = threadIdx.x, lane = tid & 31, wid = tid >> 5;
    int i = blockIdx.x * SCAN_B + tid;
    int v = (i < n) ? g_count[i] : 0;
    int x = v;
    #pragma unroll
    for (int o = 1; o < 32; o <<= 1) {
        int y = __shfl_up_sync(0xffffffffu, x, o);
        if (lane >= o) x += y;
    }
    if (lane == 31) wsum[wid] = x;
    __syncthreads();
    if (wid == 0 && lane < 8) {
        int s = wsum[lane];
        #pragma unroll
        for (int o = 1; o < 8; o <<= 1) {
            int y = __shfl_up_sync(0xffu, s, o);
            if (lane >= o) s += y;
        }
        wsum[lane] = s;
    }
    __syncthreads();
    int woff = (wid > 0) ? wsum[wid - 1] : 0;
    int off = g_bsum[blockIdx.x] + (x - v) + woff;
    if (i < n) {
        g_offsets[i] = off;
        g_cursor[i]  = off;
    }
}

// ---------------- permutation scatter into CSR slots (src only) ----------------
__global__ void k_scatter(const int* __restrict__ ei, int e, int n) {
    int i = blockIdx.x * blockDim.x + threadIdx.x;
    if (i >= e) return;
    int row = ei[i];
    int col = ei[e + i];
    row = min(max(row, 0), n - 1);
    col = min(max(col, 0), n - 1);
    int pos = atomicAdd(&g_cursor[col], 1);
    g_src_sorted[pos] = row;
}

// ---- fused: scores + softmax (shift-free) + weighted gather, warp/node ----
__global__ void k_agg(const float* __restrict__ X, int n) {
    __shared__ float sp[8][32][9];   // [warp][edge-in-group][head], pad 9
    __shared__ int   ssrc[8][32];
    int w = threadIdx.x >> 5, lane = threadIdx.x & 31;
    int node = blockIdx.x * 8 + w;
    if (node >= n) return;
    int start = g_offsets[node];
    int end   = g_offsets[node + 1];

    const float4* bd4 = (const float4*)(g_alpha_dst + (size_t)node * H);
    float4 bd0 = bd4[0], bd1 = bd4[1];

    float den[8];
    #pragma unroll
    for (int h = 0; h < 8; h++) den[h] = 0.f;
    float4 acc = make_float4(0.f, 0.f, 0.f, 0.f);
    const int hsel = lane >> 2;

    for (int j0 = start; j0 < end; j0 += 32) {
        int j = j0 + lane;
        float p[8];
        int src = 0;
        if (j < end) {
            src = g_src_sorted[j];
            const float4* as4 = (const float4*)(g_alpha_src + (size_t)src * H);
            float4 a0 = as4[0], a1 = as4[1];
            float s[8];
            s[0] = a0.x + bd0.x; s[1] = a0.y + bd0.y;
            s[2] = a0.z + bd0.z; s[3] = a0.w + bd0.w;
            s[4] = a1.x + bd1.x; s[5] = a1.y + bd1.y;
            s[6] = a1.z + bd1.z; s[7] = a1.w + bd1.w;
            #pragma unroll
            for (int h = 0; h < 8; h++) {
                float v = (s[h] >= 0.f) ? s[h] : 0.2f * s[h];
                p[h] = __expf(v);
                den[h] += p[h];
            }
        } else {
            #pragma unroll
            for (int h = 0; h < 8; h++) p[h] = 0.f;
        }
        #pragma unroll
        for (int h = 0; h < 8; h++) sp[w][lane][h] = p[h];
        ssrc[w][lane] = src;
        __syncwarp();
        int cnt = min(32, end - j0);
        #pragma unroll 4
        for (int t = 0; t < cnt; t++) {
            const float4* xr = (const float4*)(X + (size_t)ssrc[w][t] * HID);
            float pw = sp[w][t][hsel];
            float4 xv = xr[lane];
            acc.x += pw * xv.x;
            acc.y += pw * xv.y;
            acc.z += pw * xv.z;
            acc.w += pw * xv.w;
        }
        __syncwarp();
    }
    #pragma unroll
    for (int o = 16; o > 0; o >>= 1)
        #pragma unroll
        for (int h = 0; h < 8; h++)
            den[h] += __shfl_xor_sync(0xffffffffu, den[h], o);

    float inv = 1.f / (den[hsel] + 1e-10f);
    ((float4*)(g_agg + (size_t)node * HID))[lane] =
        make_float4(acc.x * inv, acc.y * inv, acc.z * inv, acc.w * inv);
}

// ---------------- out = agg @ out_w + out_b  (64x64 tiles, 4x4 micro) ----------------
__global__ void k_gemm(const float* __restrict__ W,
                       const float* __restrict__ bias,
                       float* __restrict__ out, int n) {
    __shared__ float As[16][68];
    __shared__ float Bs[16][68];
    int tx = threadIdx.x & 15;
    int ty = threadIdx.x >> 4;
    int m0 = blockIdx.x * 64;
    int c0 = blockIdx.y * 64;
    float acc[4][4];
    #pragma unroll
    for (int i = 0; i < 4; i++)
        #pragma unroll
        for (int j = 0; j < 4; j++) acc[i][j] = 0.f;

    for (int kt = 0; kt < HID; kt += 16) {
        {
            int t = threadIdx.x;
            int mm = t >> 2, q = t & 3;
            int row = m0 + mm;
            float4 v = make_float4(0.f, 0.f, 0.f, 0.f);
            if (row < n)
                v = *(const float4*)(g_agg + (size_t)row * HID + kt + q * 4);
            As[q * 4 + 0][mm] = v.x;
            As[q * 4 + 1][mm] = v.y;
            As[q * 4 + 2][mm] = v.z;
            As[q * 4 + 3][mm] = v.w;
        }
        {
            int t = threadIdx.x;
            int kk = t >> 4, cq = t & 15;
            float4 v = *(const float4*)(W + (size_t)(kt + kk) * HID + c0 + cq * 4);
            *(float4*)&Bs[kk][cq * 4] = v;
        }
        __syncthreads();
        #pragma unroll
        for (int k = 0; k < 16; k++) {
            float4 a = *(const float4*)&As[k][ty * 4];
            float4 b = *(const float4*)&Bs[k][tx * 4];
            acc[0][0] += a.x * b.x; acc[0][1] += a.x * b.y; acc[0][2] += a.x * b.z; acc[0][3] += a.x * b.w;
            acc[1][0] += a.y * b.x; acc[1][1] += a.y * b.y; acc[1][2] += a.y * b.z; acc[1][3] += a.y * b.w;
            acc[2][0] += a.z * b.x; acc[2][1] += a.z * b.y; acc[2][2] += a.z * b.z; acc[2][3] += a.z * b.w;
            acc[3][0] += a.w * b.x; acc[3][1] += a.w * b.y; acc[3][2] += a.w * b.z; acc[3][3] += a.w * b.w;
        }
        __syncthreads();
    }
    #pragma unroll
    for (int i = 0; i < 4; i++) {
        int row = m0 + ty * 4 + i;
        if (row >= n) continue;
        #pragma unroll
        for (int j = 0; j < 4; j++) {
            int c = c0 + tx * 4 + j;
            out[(size_t)row * HID + c] = acc[i][j] + bias[c];
        }
    }
}

extern "C" void kernel_launch(void* const* d_in, const int* in_sizes, int n_in,
                              void* d_out, int out_size) {
    const float* X      = (const float*)d_in[0];
    const int*   ei     = (const int*)d_in[1];
    const float* node_w = (const float*)d_in[2];
    const float* node_b = (const float*)d_in[3];
    const float* att_w  = (const float*)d_in[4];
    const float* out_w  = (const float*)d_in[5];
    const float* out_b  = (const float*)d_in[6];
    float*       out    = (float*)d_out;

    int n = in_sizes[0] / HID;
    int e = in_sizes[1] / 2;
    int nb = (n + SCAN_B - 1) / SCAN_B;

    k_init   <<<nb, SCAN_B>>>(node_w, node_b, att_w, n);
    k_alpha  <<<(n + 7) / 8, 256>>>(X, n);
    k_count  <<<(e + 255) / 256, 256>>>(ei, e, n);
    k_scan1  <<<nb, SCAN_B>>>(n);
    k_scan2  <<<1, 512>>>(nb, n);
    k_scan3  <<<nb, SCAN_B>>>(n);
    k_scatter<<<(e + 255) / 256, 256>>>(ei, e, n);
    k_agg    <<<(n + 7) / 8, 256>>>(X, n);
    dim3 gg((n + 63) / 64, HID / 64);
    k_gemm   <<<gg, 256>>>(out_w, out_b, out, n);
}